// round 9
// baseline (speedup 1.0000x reference)
#include <cuda_runtime.h>
#include <cuda_fp16.h>
#include <cstdint>

// ---------------- problem constants ----------------
constexpr int T  = 8192;
constexpr int D  = 1024;
constexpr int F  = 4096;
constexpr int E  = 8;
constexpr int TK = T * 2;

// ---------------- device scratch ----------------
__device__ int   g_top_e[TK];
__device__ float g_top_w[TK];
__device__ int   g_slot[TK];
__device__ int   g_tok[TK];
__device__ int   g_off[E + 1];

__device__ __half g_xh[(size_t)T * D];
__device__ __half g_wgu[(size_t)E * 2 * F * D];   // [e][n'=2f+b][k<D], fp16, K-major
__device__ __half g_wd[(size_t)E * D * F];        // [e][n<D][k<F]
__device__ __half g_h[(size_t)TK * F];
__device__ float  g_obuf[(size_t)TK * D];

// ---------------- helpers ----------------
__device__ __forceinline__ uint32_t smem_u32(const void* p) {
    uint32_t a;
    asm("{ .reg .u64 t; cvta.to.shared.u64 t, %1; cvt.u32.u64 %0, t; }" : "=r"(a) : "l"(p));
    return a;
}
__device__ __forceinline__ void cpa16(uint32_t s, const void* g) {
    asm volatile("cp.async.cg.shared.global [%0], [%1], 16;" :: "r"(s), "l"(g));
}
__device__ __forceinline__ void ldsm4(uint32_t* r, uint32_t addr) {
    asm volatile("ldmatrix.sync.aligned.m8n8.x4.shared.b16 {%0,%1,%2,%3}, [%4];"
        : "=r"(r[0]), "=r"(r[1]), "=r"(r[2]), "=r"(r[3]) : "r"(addr));
}
__device__ __forceinline__ void mma_fp16(float* d, const uint32_t* a, const uint32_t* b) {
    asm volatile("mma.sync.aligned.m16n8k16.row.col.f32.f16.f16.f32 "
        "{%0,%1,%2,%3}, {%4,%5,%6,%7}, {%8,%9}, {%0,%1,%2,%3};"
        : "+f"(d[0]), "+f"(d[1]), "+f"(d[2]), "+f"(d[3])
        : "r"(a[0]), "r"(a[1]), "r"(a[2]), "r"(a[3]), "r"(b[0]), "r"(b[1]));
}

// ---------------- fused prep ----------------
__global__ __launch_bounds__(256) void prep_kernel(
    const float* __restrict__ x, const float* __restrict__ gw,
    const float* __restrict__ uw, const float* __restrict__ dw)
{
    int b = blockIdx.x;
    if (b < 32768) {
        int e = b >> 12, rem = b & 4095;
        int f0 = (rem & 127) * 32, k0 = (rem >> 7) * 32;
        __shared__ float sg[32][33], su[32][33];
        int tx = threadIdx.x & 31, ty = threadIdx.x >> 5;
        const float* gs = gw + ((size_t)e * D + k0) * F + f0;
        const float* us = uw + ((size_t)e * D + k0) * F + f0;
#pragma unroll
        for (int i = 0; i < 32; i += 8) {
            sg[ty + i][tx] = gs[(size_t)(ty + i) * F + tx];
            su[ty + i][tx] = us[(size_t)(ty + i) * F + tx];
        }
        __syncthreads();
#pragma unroll
        for (int i = 0; i < 32; i += 8) {
            int fr = ty + i;
            float vg = sg[tx][fr];
            float vu = su[tx][fr];
            size_t rg = ((size_t)e * 2 * F + 2 * (f0 + fr)) * D + k0 + tx;
            size_t ru = ((size_t)e * 2 * F + 2 * (f0 + fr) + 1) * D + k0 + tx;
            g_wgu[rg] = __float2half_rn(vg);
            g_wgu[ru] = __float2half_rn(vu);
        }
    } else if (b < 65536) {
        int rem = b - 32768;
        int e = rem >> 12; rem &= 4095;
        int n0 = (rem & 31) * 32, k0 = (rem >> 5) * 32;
        __shared__ float s[32][33];
        int tx = threadIdx.x & 31, ty = threadIdx.x >> 5;
        const float* src = dw + ((size_t)e * F + k0) * D + n0;
#pragma unroll
        for (int i = 0; i < 32; i += 8)
            s[ty + i][tx] = src[(size_t)(ty + i) * D + tx];
        __syncthreads();
#pragma unroll
        for (int i = 0; i < 32; i += 8) {
            int nr = ty + i;
            float v = s[tx][nr];
            size_t r = ((size_t)e * D + n0 + nr) * F + k0 + tx;
            g_wd[r] = __float2half_rn(v);
        }
    } else {
        size_t i = (size_t)(b - 65536) * 256 + threadIdx.x;
        float4 v = ((const float4*)x)[i];
        __half h[4] = { __float2half_rn(v.x), __float2half_rn(v.y),
                        __float2half_rn(v.z), __float2half_rn(v.w) };
        *(uint2*)&g_xh[i * 4] = *(uint2*)h;
    }
}

// ---------------- router ----------------
__global__ void router_kernel(const float* __restrict__ x, const float* __restrict__ rw) {
    __shared__ float rws[E * D];
    for (int i = threadIdx.x; i < E * D; i += blockDim.x)
        rws[i] = rw[(i & (D - 1)) * E + (i >> 10)];
    __syncthreads();
    int wid = threadIdx.x >> 5, lane = threadIdx.x & 31;
    int t = blockIdx.x * 8 + wid;
    const float* xr = x + (size_t)t * D;
    float acc[E];
#pragma unroll
    for (int e = 0; e < E; e++) acc[e] = 0.f;
    for (int j = 0; j < D / 32; j++) {
        int d = j * 32 + lane;
        float xv = xr[d];
#pragma unroll
        for (int e = 0; e < E; e++) acc[e] += xv * rws[e * D + d];
    }
#pragma unroll
    for (int e = 0; e < E; e++)
#pragma unroll
        for (int o = 16; o > 0; o >>= 1)
            acc[e] += __shfl_xor_sync(0xffffffffu, acc[e], o);
    if (lane == 0) {
        float m = acc[0];
#pragma unroll
        for (int e = 1; e < E; e++) m = fmaxf(m, acc[e]);
        float p[E], s = 0.f;
#pragma unroll
        for (int e = 0; e < E; e++) { p[e] = expf(acc[e] - m); s += p[e]; }
        float inv = 1.f / s;
        int e0 = 0;
#pragma unroll
        for (int e = 1; e < E; e++) if (acc[e] > acc[e0]) e0 = e;
        int e1 = (e0 == 0) ? 1 : 0;
#pragma unroll
        for (int e = 0; e < E; e++) if (e != e0 && acc[e] > acc[e1]) e1 = e;
        g_top_e[2 * t] = e0; g_top_e[2 * t + 1] = e1;
        g_top_w[2 * t] = p[e0] * inv; g_top_w[2 * t + 1] = p[e1] * inv;
    }
}

// ---------------- per-expert token lists ----------------
__global__ void build_lists_kernel() {
    __shared__ int cnts[E];
    int wid = threadIdx.x >> 5, lane = threadIdx.x & 31;
    if (wid < E) {
        int e = wid, c = 0;
        for (int base = 0; base < T; base += 32) {
            int t = base + lane;
            bool m = (g_top_e[2 * t] == e) || (g_top_e[2 * t + 1] == e);
            c += __popc(__ballot_sync(0xffffffffu, m));
        }
        if (lane == 0) cnts[e] = c;
    }
    __syncthreads();
    if (threadIdx.x == 0) {
        int s = 0;
        for (int e = 0; e < E; e++) { g_off[e] = s; s += cnts[e]; }
        g_off[E] = s;
        for (int e = 0; e < E; e++) cnts[e] = g_off[e];
    }
    __syncthreads();
    if (wid < E) {
        int e = wid, pos = cnts[e];
        for (int base = 0; base < T; base += 32) {
            int t = base + lane;
            bool m0 = (g_top_e[2 * t] == e);
            bool m1 = (g_top_e[2 * t + 1] == e);
            bool m = m0 || m1;
            unsigned mask = __ballot_sync(0xffffffffu, m);
            if (m) {
                int idx = pos + __popc(mask & ((1u << lane) - 1));
                g_tok[idx] = t;
                g_slot[2 * t + (m0 ? 0 : 1)] = idx;
            }
            pos += __popc(mask);
        }
    }
}

// ---------------- grouped GEMM, fp16, 64x64 warp tiles ----------------
// MODE 0: BM=128, BN=256, warps 2M x 4N. A = gathered x, W = g_wgu, epi silu*up -> g_h
// MODE 1: BM=256, BN=128, warps 4M x 2N. A = g_h,        W = g_wd,  epi fp32 -> g_obuf
// 256 threads, warp tile 64x64 (acc 128 regs). 4 stages, distance-3, 1 barrier/stage.
constexpr int ROWB = 80;
constexpr int STGB = 384 * ROWB;          // (BM+BN)*80 = 30720 both modes
constexpr int GEMM_SMEM = 4 * STGB;       // 122880

template <int MODE>
__global__ __launch_bounds__(256, 1) void gemm_mma() {
    constexpr int KD  = MODE ? 4096 : 1024;
    constexpr int S   = KD / 32;
    constexpr int BM  = MODE ? 256 : 128;
    constexpr int BN  = MODE ? 128 : 256;
    constexpr int WMG = MODE ? 4 : 2;     // warps along M
    constexpr int ACH = BM / 64;          // A 16B-chunks per thread per stage
    constexpr int BCH = BN / 64;
    constexpr int BBASE = BM * ROWB;

    int e   = blockIdx.z;
    int off = g_off[e], cnt = g_off[e + 1] - off;
    int m0  = blockIdx.x * BM;
    if (m0 >= cnt) return;
    int n0  = blockIdx.y * BN;

    extern __shared__ char smem[];
    uint32_t sb = smem_u32(smem);
    int tid = threadIdx.x, wid = tid >> 5, lane = tid & 31;
    int wm = wid & (WMG - 1), wn = wid / WMG;

    const __half* Ah = MODE ? g_h : g_xh;
    const __half* W  = (MODE ? g_wd : g_wgu) + (size_t)e * (MODE ? (size_t)D * F : (size_t)2 * F * D);

    // loaders
    const __half* a_p[ACH]; uint32_t a_so[ACH];
#pragma unroll
    for (int j = 0; j < ACH; j++) {
        int ch = tid * ACH + j;
        int row = ch >> 2, col = ch & 3;
        int rr = (m0 + row < cnt) ? row : 0;
        int gr = MODE ? (off + m0 + rr) : g_tok[off + m0 + rr];
        a_p[j]  = Ah + (size_t)gr * KD + col * 8;
        a_so[j] = (uint32_t)(row * ROWB + col * 16);
    }
    const __half* b_p[BCH]; uint32_t b_so[BCH];
#pragma unroll
    for (int j = 0; j < BCH; j++) {
        int ch = tid * BCH + j;
        int row = ch >> 2, col = ch & 3;
        b_p[j]  = W + (size_t)(n0 + row) * KD + col * 8;
        b_so[j] = (uint32_t)(BBASE + row * ROWB + col * 16);
    }

    // ldmatrix offsets: 64x64 warp tile
    uint32_t aRow[4], bRow[4];
#pragma unroll
    for (int mt = 0; mt < 4; mt++) {
        int row = wm * 64 + mt * 16 + (lane & 15);
        aRow[mt] = (uint32_t)(row * ROWB + (lane >> 4) * 16);
    }
#pragma unroll
    for (int p = 0; p < 4; p++) {
        int nrow = wn * 64 + p * 16 + (lane & 7) + ((lane >> 4) << 3);
        bRow[p] = (uint32_t)(BBASE + nrow * ROWB + ((lane >> 3) & 1) * 16);
    }

    float acc[4][8][4];
#pragma unroll
    for (int a = 0; a < 4; a++)
#pragma unroll
        for (int b = 0; b < 8; b++)
#pragma unroll
            for (int c = 0; c < 4; c++) acc[a][b][c] = 0.f;

    // prologue: stages 0,1,2
#pragma unroll
    for (int p = 0; p < 3; p++) {
        uint32_t base = sb + p * STGB;
        int k = p * 32;
#pragma unroll
        for (int j = 0; j < ACH; j++) cpa16(base + a_so[j], a_p[j] + k);
#pragma unroll
        for (int j = 0; j < BCH; j++) cpa16(base + b_so[j], b_p[j] + k);
        asm volatile("cp.async.commit_group;" ::: "memory");
    }

    for (int s = 0; s < S; s++) {
        int rem = S - 1 - s;
        if (rem >= 2)      asm volatile("cp.async.wait_group 2;" ::: "memory");
        else if (rem == 1) asm volatile("cp.async.wait_group 1;" ::: "memory");
        else               asm volatile("cp.async.wait_group 0;" ::: "memory");
        __syncthreads();

        if (s + 3 < S) {
            int k = (s + 3) * 32;
            uint32_t base = sb + ((s + 3) & 3) * STGB;
#pragma unroll
            for (int j = 0; j < ACH; j++) cpa16(base + a_so[j], a_p[j] + k);
#pragma unroll
            for (int j = 0; j < BCH; j++) cpa16(base + b_so[j], b_p[j] + k);
            asm volatile("cp.async.commit_group;" ::: "memory");
        }

        uint32_t base = sb + (s & 3) * STGB;
        uint32_t ah[2][4][4], bb[2][4][4];
#pragma unroll
        for (int kk = 0; kk < 2; kk++) {
#pragma unroll
            for (int mt = 0; mt < 4; mt++) ldsm4(ah[kk][mt], base + aRow[mt] + kk * 32);
#pragma unroll
            for (int p = 0; p < 4; p++)   ldsm4(bb[kk][p],  base + bRow[p]  + kk * 32);
        }
#pragma unroll
        for (int kk = 0; kk < 2; kk++)
#pragma unroll
            for (int mt = 0; mt < 4; mt++)
#pragma unroll
                for (int nt = 0; nt < 8; nt++) {
                    const uint32_t* pb = &bb[kk][nt >> 1][(nt & 1) * 2];
                    mma_fp16(acc[mt][nt], ah[kk][mt], pb);
                }
    }

    // ---------------- epilogue ----------------
#pragma unroll
    for (int mt = 0; mt < 4; mt++) {
        int local0 = wm * 64 + mt * 16 + (lane >> 2);
        int local1 = local0 + 8;
        bool v0 = (m0 + local0) < cnt;
        bool v1 = (m0 + local1) < cnt;
        size_t s0 = (size_t)(off + m0 + local0);
        size_t s1 = (size_t)(off + m0 + local1);
        if (MODE == 0) {
#pragma unroll
            for (int nt = 0; nt < 8; nt++) {
                int f = ((n0 + wn * 64 + nt * 8) >> 1) + (lane & 3);
                float g0 = acc[mt][nt][0], u0 = acc[mt][nt][1];
                float g1 = acc[mt][nt][2], u1 = acc[mt][nt][3];
                float h0 = g0 / (1.f + expf(-g0)) * u0;
                float h1 = g1 / (1.f + expf(-g1)) * u1;
                if (v0) g_h[s0 * F + f] = __float2half_rn(h0);
                if (v1) g_h[s1 * F + f] = __float2half_rn(h1);
            }
        } else {
#pragma unroll
            for (int nt = 0; nt < 8; nt++) {
                int col = n0 + wn * 64 + nt * 8 + (lane & 3) * 2;
                if (v0) *(float2*)&g_obuf[s0 * D + col] = make_float2(acc[mt][nt][0], acc[mt][nt][1]);
                if (v1) *(float2*)&g_obuf[s1 * D + col] = make_float2(acc[mt][nt][2], acc[mt][nt][3]);
            }
        }
    }
}

// ---------------- combine ----------------
__global__ void combine_kernel(float* __restrict__ out) {
    int t = blockIdx.x;
    float w0 = g_top_w[2 * t], w1 = g_top_w[2 * t + 1];
    const float* r0 = g_obuf + (size_t)g_slot[2 * t] * D;
    const float* r1 = g_obuf + (size_t)g_slot[2 * t + 1] * D;
    int c = threadIdx.x * 4;
    float4 a = *(const float4*)(r0 + c);
    float4 b = *(const float4*)(r1 + c);
    float4 o;
    o.x = w0 * a.x + w1 * b.x;
    o.y = w0 * a.y + w1 * b.y;
    o.z = w0 * a.z + w1 * b.z;
    o.w = w0 * a.w + w1 * b.w;
    *(float4*)(out + (size_t)t * D + c) = o;
}

// ---------------- launch ----------------
extern "C" void kernel_launch(void* const* d_in, const int* in_sizes, int n_in,
                              void* d_out, int out_size) {
    const float* x  = (const float*)d_in[0];
    const float* rw = (const float*)d_in[1];
    const float* gw = (const float*)d_in[2];
    const float* uw = (const float*)d_in[3];
    const float* dw = (const float*)d_in[4];
    float* out = (float*)d_out;

    cudaFuncSetAttribute(gemm_mma<0>, cudaFuncAttributeMaxDynamicSharedMemorySize, GEMM_SMEM);
    cudaFuncSetAttribute(gemm_mma<1>, cudaFuncAttributeMaxDynamicSharedMemorySize, GEMM_SMEM);

    prep_kernel<<<73728, 256>>>(x, gw, uw, dw);                 // 1
    router_kernel<<<T / 8, 256>>>(x, rw);                        // 2
    build_lists_kernel<<<1, 256>>>();                            // 3
    gemm_mma<0><<<dim3(32, 32, E), 256, GEMM_SMEM>>>();          // 4  <- profiled
    gemm_mma<1><<<dim3(16, 8, E), 256, GEMM_SMEM>>>();           // 5
    combine_kernel<<<T, 256>>>(out);                             // 6
}

// round 10
// speedup vs baseline: 1.3953x; 1.3953x over previous
#include <cuda_runtime.h>
#include <cuda_fp16.h>
#include <cstdint>

// ---------------- problem constants ----------------
constexpr int T  = 8192;
constexpr int D  = 1024;
constexpr int F  = 4096;
constexpr int E  = 8;
constexpr int TK = T * 2;

// ---------------- device scratch ----------------
__device__ int   g_top_e[TK];
__device__ float g_top_w[TK];
__device__ int   g_slot[TK];
__device__ int   g_tok[TK];
__device__ int   g_off[E + 1];

__device__ __half g_xh[(size_t)T * D];
__device__ __half g_wgu[(size_t)E * 2 * F * D];   // [e][n'=2f+b][k<D], fp16, K-major
__device__ __half g_wd[(size_t)E * D * F];        // [e][n<D][k<F]
__device__ __half g_h[(size_t)TK * F];
__device__ float  g_obuf[(size_t)TK * D];

// ---------------- helpers ----------------
__device__ __forceinline__ uint32_t smem_u32(const void* p) {
    uint32_t a;
    asm("{ .reg .u64 t; cvta.to.shared.u64 t, %1; cvt.u32.u64 %0, t; }" : "=r"(a) : "l"(p));
    return a;
}
__device__ __forceinline__ void cpa16(uint32_t s, const void* g) {
    asm volatile("cp.async.cg.shared.global [%0], [%1], 16;" :: "r"(s), "l"(g));
}
__device__ __forceinline__ void ldsm4(uint32_t* r, uint32_t addr) {
    asm volatile("ldmatrix.sync.aligned.m8n8.x4.shared.b16 {%0,%1,%2,%3}, [%4];"
        : "=r"(r[0]), "=r"(r[1]), "=r"(r[2]), "=r"(r[3]) : "r"(addr));
}
__device__ __forceinline__ void mma_fp16(float* d, const uint32_t* a, const uint32_t* b) {
    asm volatile("mma.sync.aligned.m16n8k16.row.col.f32.f16.f16.f32 "
        "{%0,%1,%2,%3}, {%4,%5,%6,%7}, {%8,%9}, {%0,%1,%2,%3};"
        : "+f"(d[0]), "+f"(d[1]), "+f"(d[2]), "+f"(d[3])
        : "r"(a[0]), "r"(a[1]), "r"(a[2]), "r"(a[3]), "r"(b[0]), "r"(b[1]));
}

// ---------------- fused weight prep ----------------
__global__ __launch_bounds__(256) void prep_kernel(
    const float* __restrict__ gw, const float* __restrict__ uw,
    const float* __restrict__ dw)
{
    int b = blockIdx.x;
    if (b < 32768) {
        int e = b >> 12, rem = b & 4095;
        int f0 = (rem & 127) * 32, k0 = (rem >> 7) * 32;
        __shared__ float sg[32][33], su[32][33];
        int tx = threadIdx.x & 31, ty = threadIdx.x >> 5;
        const float* gs = gw + ((size_t)e * D + k0) * F + f0;
        const float* us = uw + ((size_t)e * D + k0) * F + f0;
#pragma unroll
        for (int i = 0; i < 32; i += 8) {
            sg[ty + i][tx] = gs[(size_t)(ty + i) * F + tx];
            su[ty + i][tx] = us[(size_t)(ty + i) * F + tx];
        }
        __syncthreads();
#pragma unroll
        for (int i = 0; i < 32; i += 8) {
            int fr = ty + i;
            float vg = sg[tx][fr];
            float vu = su[tx][fr];
            size_t rg = ((size_t)e * 2 * F + 2 * (f0 + fr)) * D + k0 + tx;
            size_t ru = ((size_t)e * 2 * F + 2 * (f0 + fr) + 1) * D + k0 + tx;
            g_wgu[rg] = __float2half_rn(vg);
            g_wgu[ru] = __float2half_rn(vu);
        }
    } else {
        int rem = b - 32768;
        int e = rem >> 12; rem &= 4095;
        int n0 = (rem & 31) * 32, k0 = (rem >> 5) * 32;
        __shared__ float s[32][33];
        int tx = threadIdx.x & 31, ty = threadIdx.x >> 5;
        const float* src = dw + ((size_t)e * F + k0) * D + n0;
#pragma unroll
        for (int i = 0; i < 32; i += 8)
            s[ty + i][tx] = src[(size_t)(ty + i) * D + tx];
        __syncthreads();
#pragma unroll
        for (int i = 0; i < 32; i += 8) {
            int nr = ty + i;
            float v = s[tx][nr];
            size_t r = ((size_t)e * D + n0 + nr) * F + k0 + tx;
            g_wd[r] = __float2half_rn(v);
        }
    }
}

// ---------------- router (+ x fp16 cast fused) ----------------
__global__ void router_kernel(const float* __restrict__ x, const float* __restrict__ rw) {
    __shared__ float rws[E * D];
    for (int i = threadIdx.x; i < E * D; i += blockDim.x)
        rws[i] = rw[(i & (D - 1)) * E + (i >> 10)];
    __syncthreads();
    int wid = threadIdx.x >> 5, lane = threadIdx.x & 31;
    int t = blockIdx.x * 8 + wid;
    const float* xr = x + (size_t)t * D;
    float acc[E];
#pragma unroll
    for (int e = 0; e < E; e++) acc[e] = 0.f;
    for (int j = 0; j < D / 32; j++) {
        int d = j * 32 + lane;
        float xv = xr[d];
        g_xh[(size_t)t * D + d] = __float2half_rn(xv);   // fused x cast
#pragma unroll
        for (int e = 0; e < E; e++) acc[e] += xv * rws[e * D + d];
    }
#pragma unroll
    for (int e = 0; e < E; e++)
#pragma unroll
        for (int o = 16; o > 0; o >>= 1)
            acc[e] += __shfl_xor_sync(0xffffffffu, acc[e], o);
    if (lane == 0) {
        float m = acc[0];
#pragma unroll
        for (int e = 1; e < E; e++) m = fmaxf(m, acc[e]);
        float p[E], s = 0.f;
#pragma unroll
        for (int e = 0; e < E; e++) { p[e] = expf(acc[e] - m); s += p[e]; }
        float inv = 1.f / s;
        int e0 = 0;
#pragma unroll
        for (int e = 1; e < E; e++) if (acc[e] > acc[e0]) e0 = e;
        int e1 = (e0 == 0) ? 1 : 0;
#pragma unroll
        for (int e = 0; e < E; e++) if (e != e0 && acc[e] > acc[e1]) e1 = e;
        g_top_e[2 * t] = e0; g_top_e[2 * t + 1] = e1;
        g_top_w[2 * t] = p[e0] * inv; g_top_w[2 * t + 1] = p[e1] * inv;
    }
}

// ---------------- per-expert token lists ----------------
__global__ void build_lists_kernel() {
    __shared__ int cnts[E];
    int wid = threadIdx.x >> 5, lane = threadIdx.x & 31;
    if (wid < E) {
        int e = wid, c = 0;
        for (int base = 0; base < T; base += 32) {
            int t = base + lane;
            bool m = (g_top_e[2 * t] == e) || (g_top_e[2 * t + 1] == e);
            c += __popc(__ballot_sync(0xffffffffu, m));
        }
        if (lane == 0) cnts[e] = c;
    }
    __syncthreads();
    if (threadIdx.x == 0) {
        int s = 0;
        for (int e = 0; e < E; e++) { g_off[e] = s; s += cnts[e]; }
        g_off[E] = s;
        for (int e = 0; e < E; e++) cnts[e] = g_off[e];
    }
    __syncthreads();
    if (wid < E) {
        int e = wid, pos = cnts[e];
        for (int base = 0; base < T; base += 32) {
            int t = base + lane;
            bool m0 = (g_top_e[2 * t] == e);
            bool m1 = (g_top_e[2 * t + 1] == e);
            bool m = m0 || m1;
            unsigned mask = __ballot_sync(0xffffffffu, m);
            if (m) {
                int idx = pos + __popc(mask & ((1u << lane) - 1));
                g_tok[idx] = t;
                g_slot[2 * t + (m0 ? 0 : 1)] = idx;
            }
            pos += __popc(mask);
        }
    }
}

// ---------------- grouped GEMM, fp16 via mma.sync ----------------
// BM=128, BN=128, BK=32. 256 threads = 8 warps (4 M x 2 N), warp tile 32x64.
// 5 stages, prefetch distance 4, ONE barrier per stage. 100KB smem, 2 CTAs/SM.
constexpr int ROWB  = 80;
constexpr int AMATB = 128 * ROWB;            // 10240
constexpr int STGB  = 2 * AMATB;             // 20480
constexpr int NSTG  = 5;
constexpr int GEMM_SMEM = NSTG * STGB;       // 102400

template <int MODE>
__global__ __launch_bounds__(256, 2) void gemm_mma() {
    constexpr int KD = MODE ? 4096 : 1024;
    constexpr int S  = KD / 32;

    int e   = blockIdx.z;
    int off = g_off[e], cnt = g_off[e + 1] - off;
    int m0  = blockIdx.x * 128;
    if (m0 >= cnt) return;
    int n0  = blockIdx.y * 128;

    extern __shared__ char smem[];
    uint32_t sb = smem_u32(smem);
    int tid = threadIdx.x, wid = tid >> 5, lane = tid & 31;
    int wm = wid & 3, wn = wid >> 2;

    const __half* Ah = MODE ? g_h : g_xh;
    const __half* W  = (MODE ? g_wd : g_wgu) + (size_t)e * (MODE ? (size_t)D * F : (size_t)2 * F * D);

    int ar0 = tid >> 2, ac0 = tid & 3;
    int ar1 = ar0 + 64;
    int rr0 = (m0 + ar0 < cnt) ? ar0 : 0;
    int rr1 = (m0 + ar1 < cnt) ? ar1 : 0;
    int gr0 = MODE ? (off + m0 + rr0) : g_tok[off + m0 + rr0];
    int gr1 = MODE ? (off + m0 + rr1) : g_tok[off + m0 + rr1];
    const __half* a_p0 = Ah + (size_t)gr0 * KD + ac0 * 8;
    const __half* a_p1 = Ah + (size_t)gr1 * KD + ac0 * 8;
    uint32_t aoff0 = (uint32_t)(ar0 * ROWB + ac0 * 16);
    uint32_t aoff1 = (uint32_t)(ar1 * ROWB + ac0 * 16);
    const __half* b_p0 = W + (size_t)(n0 + ar0) * KD + ac0 * 8;
    const __half* b_p1 = W + (size_t)(n0 + ar1) * KD + ac0 * 8;
    uint32_t boff0 = (uint32_t)(AMATB + ar0 * ROWB + ac0 * 16);
    uint32_t boff1 = (uint32_t)(AMATB + ar1 * ROWB + ac0 * 16);

    uint32_t aRow[2], bRow[4];
#pragma unroll
    for (int mt = 0; mt < 2; mt++) {
        int row = wm * 32 + mt * 16 + (lane & 15);
        aRow[mt] = (uint32_t)(row * ROWB + (lane >> 4) * 16);
    }
#pragma unroll
    for (int p = 0; p < 4; p++) {
        int nrow = wn * 64 + p * 16 + (lane & 7) + ((lane >> 4) << 3);
        bRow[p] = (uint32_t)(AMATB + nrow * ROWB + ((lane >> 3) & 1) * 16);
    }

    float acc[2][8][4];
#pragma unroll
    for (int a = 0; a < 2; a++)
#pragma unroll
        for (int b = 0; b < 8; b++)
#pragma unroll
            for (int c = 0; c < 4; c++) acc[a][b][c] = 0.f;

    // prologue: stages 0..3
#pragma unroll
    for (int p = 0; p < 4; p++) {
        uint32_t base = sb + p * STGB;
        int k = p * 32;
        cpa16(base + aoff0, a_p0 + k);
        cpa16(base + aoff1, a_p1 + k);
        cpa16(base + boff0, b_p0 + k);
        cpa16(base + boff1, b_p1 + k);
        asm volatile("cp.async.commit_group;" ::: "memory");
    }

    int cur = 0;   // buffer holding stage s
    for (int s = 0; s < S; s++) {
        int rem = S - 1 - s;
        if (rem >= 3)      asm volatile("cp.async.wait_group 3;" ::: "memory");
        else if (rem == 2) asm volatile("cp.async.wait_group 2;" ::: "memory");
        else if (rem == 1) asm volatile("cp.async.wait_group 1;" ::: "memory");
        else               asm volatile("cp.async.wait_group 0;" ::: "memory");
        __syncthreads();   // gates reads of stage s AND reuse of buffer cur-1

        uint32_t base = sb + cur * STGB;
        // fragments FIRST (LDS latency overlaps with prefetch + MMA issue)
        uint32_t ah[2][2][4], bb[2][4][4];
#pragma unroll
        for (int kk = 0; kk < 2; kk++) {
            ldsm4(ah[kk][0], base + aRow[0] + kk * 32);
            ldsm4(ah[kk][1], base + aRow[1] + kk * 32);
            ldsm4(bb[kk][0], base + bRow[0] + kk * 32);
            ldsm4(bb[kk][1], base + bRow[1] + kk * 32);
            ldsm4(bb[kk][2], base + bRow[2] + kk * 32);
            ldsm4(bb[kk][3], base + bRow[3] + kk * 32);
        }

        if (s + 4 < S) {
            int k = (s + 4) * 32;
            int pbuf = (cur == 0) ? (NSTG - 1) : (cur - 1);   // (s+4) % 5
            uint32_t pb = sb + pbuf * STGB;
            cpa16(pb + aoff0, a_p0 + k);
            cpa16(pb + aoff1, a_p1 + k);
            cpa16(pb + boff0, b_p0 + k);
            cpa16(pb + boff1, b_p1 + k);
            asm volatile("cp.async.commit_group;" ::: "memory");
        }

#pragma unroll
        for (int kk = 0; kk < 2; kk++)
#pragma unroll
            for (int mt = 0; mt < 2; mt++)
#pragma unroll
                for (int nt = 0; nt < 8; nt++) {
                    const uint32_t* pb = &bb[kk][nt >> 1][(nt & 1) * 2];
                    mma_fp16(acc[mt][nt], ah[kk][mt], pb);
                }

        cur = (cur + 1 == NSTG) ? 0 : cur + 1;
    }

    // ---------------- epilogue ----------------
#pragma unroll
    for (int mt = 0; mt < 2; mt++) {
        int local0 = wm * 32 + mt * 16 + (lane >> 2);
        int local1 = local0 + 8;
        bool v0 = (m0 + local0) < cnt;
        bool v1 = (m0 + local1) < cnt;
        size_t s0 = (size_t)(off + m0 + local0);
        size_t s1 = (size_t)(off + m0 + local1);
        if (MODE == 0) {
#pragma unroll
            for (int nt = 0; nt < 8; nt++) {
                int f = ((n0 + wn * 64 + nt * 8) >> 1) + (lane & 3);
                float g0 = acc[mt][nt][0], u0 = acc[mt][nt][1];
                float g1 = acc[mt][nt][2], u1 = acc[mt][nt][3];
                float h0 = g0 / (1.f + expf(-g0)) * u0;
                float h1 = g1 / (1.f + expf(-g1)) * u1;
                if (v0) g_h[s0 * F + f] = __float2half_rn(h0);
                if (v1) g_h[s1 * F + f] = __float2half_rn(h1);
            }
        } else {
#pragma unroll
            for (int nt = 0; nt < 8; nt++) {
                int col = n0 + wn * 64 + nt * 8 + (lane & 3) * 2;
                if (v0) *(float2*)&g_obuf[s0 * D + col] = make_float2(acc[mt][nt][0], acc[mt][nt][1]);
                if (v1) *(float2*)&g_obuf[s1 * D + col] = make_float2(acc[mt][nt][2], acc[mt][nt][3]);
            }
        }
    }
}

// ---------------- combine ----------------
__global__ void combine_kernel(float* __restrict__ out) {
    int t = blockIdx.x;
    float w0 = g_top_w[2 * t], w1 = g_top_w[2 * t + 1];
    const float* r0 = g_obuf + (size_t)g_slot[2 * t] * D;
    const float* r1 = g_obuf + (size_t)g_slot[2 * t + 1] * D;
    int c = threadIdx.x * 4;
    float4 a = *(const float4*)(r0 + c);
    float4 b = *(const float4*)(r1 + c);
    float4 o;
    o.x = w0 * a.x + w1 * b.x;
    o.y = w0 * a.y + w1 * b.y;
    o.z = w0 * a.z + w1 * b.z;
    o.w = w0 * a.w + w1 * b.w;
    *(float4*)(out + (size_t)t * D + c) = o;
}

// ---------------- launch ----------------
extern "C" void kernel_launch(void* const* d_in, const int* in_sizes, int n_in,
                              void* d_out, int out_size) {
    const float* x  = (const float*)d_in[0];
    const float* rw = (const float*)d_in[1];
    const float* gw = (const float*)d_in[2];
    const float* uw = (const float*)d_in[3];
    const float* dw = (const float*)d_in[4];
    float* out = (float*)d_out;

    cudaFuncSetAttribute(gemm_mma<0>, cudaFuncAttributeMaxDynamicSharedMemorySize, GEMM_SMEM);
    cudaFuncSetAttribute(gemm_mma<1>, cudaFuncAttributeMaxDynamicSharedMemorySize, GEMM_SMEM);

    prep_kernel<<<65536, 256>>>(gw, uw, dw);                    // 1
    router_kernel<<<T / 8, 256>>>(x, rw);                        // 2
    build_lists_kernel<<<1, 256>>>();                            // 3
    gemm_mma<0><<<dim3(64, 64, E), 256, GEMM_SMEM>>>();          // 4  <- profiled
    gemm_mma<1><<<dim3(64, 8, E), 256, GEMM_SMEM>>>();           // 5
    combine_kernel<<<T, 256>>>(out);                             // 6
}

// round 11
// speedup vs baseline: 1.4991x; 1.0744x over previous
#include <cuda_runtime.h>
#include <cuda_fp16.h>
#include <cstdint>

// ---------------- problem constants ----------------
constexpr int T  = 8192;
constexpr int D  = 1024;
constexpr int F  = 4096;
constexpr int E  = 8;
constexpr int TK = T * 2;

// ---------------- device scratch ----------------
__device__ int   g_top_e[TK];
__device__ float g_top_w[TK];
__device__ int   g_slot[TK];
__device__ int   g_tok[TK];
__device__ int   g_off[E + 1];

__device__ __half g_xh[(size_t)T * D];
__device__ __half g_wgu[(size_t)E * 2 * F * D];   // [e][n'=2f+b][k<D], fp16, K-major
__device__ __half g_wd[(size_t)E * D * F];        // [e][n<D][k<F]
__device__ __half g_h[(size_t)TK * F];
__device__ float  g_obuf[(size_t)TK * D];

// ---------------- helpers ----------------
__device__ __forceinline__ uint32_t smem_u32(const void* p) {
    uint32_t a;
    asm("{ .reg .u64 t; cvta.to.shared.u64 t, %1; cvt.u32.u64 %0, t; }" : "=r"(a) : "l"(p));
    return a;
}
__device__ __forceinline__ void cpa16(uint32_t s, const void* g) {
    asm volatile("cp.async.cg.shared.global [%0], [%1], 16;" :: "r"(s), "l"(g));
}
__device__ __forceinline__ void ldsm4(uint32_t* r, uint32_t addr) {
    asm volatile("ldmatrix.sync.aligned.m8n8.x4.shared.b16 {%0,%1,%2,%3}, [%4];"
        : "=r"(r[0]), "=r"(r[1]), "=r"(r[2]), "=r"(r[3]) : "r"(addr));
}
__device__ __forceinline__ void mma_fp16(float* d, const uint32_t* a, const uint32_t* b) {
    asm volatile("mma.sync.aligned.m16n8k16.row.col.f32.f16.f16.f32 "
        "{%0,%1,%2,%3}, {%4,%5,%6,%7}, {%8,%9}, {%0,%1,%2,%3};"
        : "+f"(d[0]), "+f"(d[1]), "+f"(d[2]), "+f"(d[3])
        : "r"(a[0]), "r"(a[1]), "r"(a[2]), "r"(a[3]), "r"(b[0]), "r"(b[1]));
}

// ---------------- fused weight prep (gate/up interleave + down transpose) ----------------
__global__ __launch_bounds__(256) void prep_kernel(
    const float* __restrict__ gw, const float* __restrict__ uw,
    const float* __restrict__ dw)
{
    int b = blockIdx.x;
    if (b < 32768) {
        int e = b >> 12, rem = b & 4095;
        int f0 = (rem & 127) * 32, k0 = (rem >> 7) * 32;
        __shared__ float sg[32][33], su[32][33];
        int tx = threadIdx.x & 31, ty = threadIdx.x >> 5;
        const float* gs = gw + ((size_t)e * D + k0) * F + f0;
        const float* us = uw + ((size_t)e * D + k0) * F + f0;
#pragma unroll
        for (int i = 0; i < 32; i += 8) {
            sg[ty + i][tx] = gs[(size_t)(ty + i) * F + tx];
            su[ty + i][tx] = us[(size_t)(ty + i) * F + tx];
        }
        __syncthreads();
#pragma unroll
        for (int i = 0; i < 32; i += 8) {
            int fr = ty + i;
            float vg = sg[tx][fr];
            float vu = su[tx][fr];
            size_t rg = ((size_t)e * 2 * F + 2 * (f0 + fr)) * D + k0 + tx;
            size_t ru = ((size_t)e * 2 * F + 2 * (f0 + fr) + 1) * D + k0 + tx;
            g_wgu[rg] = __float2half_rn(vg);
            g_wgu[ru] = __float2half_rn(vu);
        }
    } else {
        int rem = b - 32768;
        int e = rem >> 12; rem &= 4095;
        int n0 = (rem & 31) * 32, k0 = (rem >> 5) * 32;
        __shared__ float s[32][33];
        int tx = threadIdx.x & 31, ty = threadIdx.x >> 5;
        const float* src = dw + ((size_t)e * F + k0) * D + n0;
#pragma unroll
        for (int i = 0; i < 32; i += 8)
            s[ty + i][tx] = src[(size_t)(ty + i) * D + tx];
        __syncthreads();
#pragma unroll
        for (int i = 0; i < 32; i += 8) {
            int nr = ty + i;
            float v = s[tx][nr];
            size_t r = ((size_t)e * D + n0 + nr) * F + k0 + tx;
            g_wd[r] = __float2half_rn(v);
        }
    }
}

// ---------------- router (+ x fp16 cast fused) ----------------
__global__ void router_kernel(const float* __restrict__ x, const float* __restrict__ rw) {
    __shared__ float rws[E * D];
    for (int i = threadIdx.x; i < E * D; i += blockDim.x)
        rws[i] = rw[(i & (D - 1)) * E + (i >> 10)];
    __syncthreads();
    int wid = threadIdx.x >> 5, lane = threadIdx.x & 31;
    int t = blockIdx.x * 8 + wid;
    const float* xr = x + (size_t)t * D;
    float acc[E];
#pragma unroll
    for (int e = 0; e < E; e++) acc[e] = 0.f;
    for (int j = 0; j < D / 32; j++) {
        int d = j * 32 + lane;
        float xv = xr[d];
        g_xh[(size_t)t * D + d] = __float2half_rn(xv);   // fused x cast
#pragma unroll
        for (int e = 0; e < E; e++) acc[e] += xv * rws[e * D + d];
    }
#pragma unroll
    for (int e = 0; e < E; e++)
#pragma unroll
        for (int o = 16; o > 0; o >>= 1)
            acc[e] += __shfl_xor_sync(0xffffffffu, acc[e], o);
    if (lane == 0) {
        float m = acc[0];
#pragma unroll
        for (int e = 1; e < E; e++) m = fmaxf(m, acc[e]);
        float p[E], s = 0.f;
#pragma unroll
        for (int e = 0; e < E; e++) { p[e] = expf(acc[e] - m); s += p[e]; }
        float inv = 1.f / s;
        int e0 = 0;
#pragma unroll
        for (int e = 1; e < E; e++) if (acc[e] > acc[e0]) e0 = e;
        int e1 = (e0 == 0) ? 1 : 0;
#pragma unroll
        for (int e = 0; e < E; e++) if (e != e0 && acc[e] > acc[e1]) e1 = e;
        g_top_e[2 * t] = e0; g_top_e[2 * t + 1] = e1;
        g_top_w[2 * t] = p[e0] * inv; g_top_w[2 * t + 1] = p[e1] * inv;
    }
}

// ---------------- per-expert token lists ----------------
__global__ void build_lists_kernel() {
    __shared__ int cnts[E];
    int wid = threadIdx.x >> 5, lane = threadIdx.x & 31;
    if (wid < E) {
        int e = wid, c = 0;
        for (int base = 0; base < T; base += 32) {
            int t = base + lane;
            bool m = (g_top_e[2 * t] == e) || (g_top_e[2 * t + 1] == e);
            c += __popc(__ballot_sync(0xffffffffu, m));
        }
        if (lane == 0) cnts[e] = c;
    }
    __syncthreads();
    if (threadIdx.x == 0) {
        int s = 0;
        for (int e = 0; e < E; e++) { g_off[e] = s; s += cnts[e]; }
        g_off[E] = s;
        for (int e = 0; e < E; e++) cnts[e] = g_off[e];
    }
    __syncthreads();
    if (wid < E) {
        int e = wid, pos = cnts[e];
        for (int base = 0; base < T; base += 32) {
            int t = base + lane;
            bool m0 = (g_top_e[2 * t] == e);
            bool m1 = (g_top_e[2 * t + 1] == e);
            bool m = m0 || m1;
            unsigned mask = __ballot_sync(0xffffffffu, m);
            if (m) {
                int idx = pos + __popc(mask & ((1u << lane) - 1));
                g_tok[idx] = t;
                g_slot[2 * t + (m0 ? 0 : 1)] = idx;
            }
            pos += __popc(mask);
        }
    }
}

// ---------------- grouped GEMM, fp16 via mma.sync (round-7 validated design) ----------------
// BM=128, BN=128, BK=32. 256 threads = 8 warps (4 M x 2 N), warp tile 32x64.
// 4 stages, prefetch distance 3, ONE barrier per stage, branch-free steady loop.
// 80KB smem, 2 CTAs/SM.
constexpr int ROWB  = 80;
constexpr int AMATB = 128 * ROWB;            // 10240
constexpr int STGB  = 2 * AMATB;             // 20480
constexpr int GEMM_SMEM = 4 * STGB;          // 81920

template <int MODE>
__global__ __launch_bounds__(256, 2) void gemm_mma() {
    constexpr int KD = MODE ? 4096 : 1024;
    constexpr int S  = KD / 32;

    int e   = blockIdx.z;
    int off = g_off[e], cnt = g_off[e + 1] - off;
    int m0  = blockIdx.x * 128;
    if (m0 >= cnt) return;
    int n0  = blockIdx.y * 128;

    extern __shared__ char smem[];
    uint32_t sb = smem_u32(smem);
    int tid = threadIdx.x, wid = tid >> 5, lane = tid & 31;
    int wm = wid & 3, wn = wid >> 2;

    const __half* Ah = MODE ? g_h : g_xh;
    const __half* W  = (MODE ? g_wd : g_wgu) + (size_t)e * (MODE ? (size_t)D * F : (size_t)2 * F * D);

    int ar0 = tid >> 2, ac0 = tid & 3;
    int ar1 = ar0 + 64;
    int rr0 = (m0 + ar0 < cnt) ? ar0 : 0;
    int rr1 = (m0 + ar1 < cnt) ? ar1 : 0;
    int gr0 = MODE ? (off + m0 + rr0) : g_tok[off + m0 + rr0];
    int gr1 = MODE ? (off + m0 + rr1) : g_tok[off + m0 + rr1];
    const __half* a_p0 = Ah + (size_t)gr0 * KD + ac0 * 8;
    const __half* a_p1 = Ah + (size_t)gr1 * KD + ac0 * 8;
    uint32_t aoff0 = (uint32_t)(ar0 * ROWB + ac0 * 16);
    uint32_t aoff1 = (uint32_t)(ar1 * ROWB + ac0 * 16);
    const __half* b_p0 = W + (size_t)(n0 + ar0) * KD + ac0 * 8;
    const __half* b_p1 = W + (size_t)(n0 + ar1) * KD + ac0 * 8;
    uint32_t boff0 = (uint32_t)(AMATB + ar0 * ROWB + ac0 * 16);
    uint32_t boff1 = (uint32_t)(AMATB + ar1 * ROWB + ac0 * 16);

    uint32_t aRow[2], bRow[4];
#pragma unroll
    for (int mt = 0; mt < 2; mt++) {
        int row = wm * 32 + mt * 16 + (lane & 15);
        aRow[mt] = (uint32_t)(row * ROWB + (lane >> 4) * 16);
    }
#pragma unroll
    for (int p = 0; p < 4; p++) {
        int nrow = wn * 64 + p * 16 + (lane & 7) + ((lane >> 4) << 3);
        bRow[p] = (uint32_t)(AMATB + nrow * ROWB + ((lane >> 3) & 1) * 16);
    }

    float acc[2][8][4];
#pragma unroll
    for (int a = 0; a < 2; a++)
#pragma unroll
        for (int b = 0; b < 8; b++)
#pragma unroll
            for (int c = 0; c < 4; c++) acc[a][b][c] = 0.f;

    auto prefetch = [&](int s) {
        int k = s * 32;
        uint32_t base = sb + (s & 3) * STGB;
        cpa16(base + aoff0, a_p0 + k);
        cpa16(base + aoff1, a_p1 + k);
        cpa16(base + boff0, b_p0 + k);
        cpa16(base + boff1, b_p1 + k);
        asm volatile("cp.async.commit_group;" ::: "memory");
    };
    auto compute = [&](int s) {
        uint32_t base = sb + (s & 3) * STGB;
#pragma unroll
        for (int kk = 0; kk < 2; kk++) {
            uint32_t ah[2][4], bb[4][4];
            ldsm4(ah[0], base + aRow[0] + kk * 32);
            ldsm4(ah[1], base + aRow[1] + kk * 32);
            ldsm4(bb[0], base + bRow[0] + kk * 32);
            ldsm4(bb[1], base + bRow[1] + kk * 32);
            ldsm4(bb[2], base + bRow[2] + kk * 32);
            ldsm4(bb[3], base + bRow[3] + kk * 32);
#pragma unroll
            for (int mt = 0; mt < 2; mt++)
#pragma unroll
                for (int nt = 0; nt < 8; nt++) {
                    const uint32_t* pb = &bb[nt >> 1][(nt & 1) * 2];
                    mma_fp16(acc[mt][nt], ah[kk == 0 ? mt : mt], pb);   // ah local to kk
                }
        }
    };

    // NOTE: compute() uses ah from its own kk scope; rewrite inline to keep per-kk liveness.
    // prologue: stages 0,1,2
    prefetch(0); prefetch(1); prefetch(2);

    int s = 0;
    // steady state: constant wait, branch-free body
#pragma unroll 1
    for (; s < S - 3; s++) {
        asm volatile("cp.async.wait_group 2;" ::: "memory");
        __syncthreads();
        prefetch(s + 3);
        compute(s);
    }
    // drain: 3 fixed iterations
    asm volatile("cp.async.wait_group 2;" ::: "memory");
    __syncthreads();
    compute(S - 3);
    asm volatile("cp.async.wait_group 1;" ::: "memory");
    __syncthreads();
    compute(S - 2);
    asm volatile("cp.async.wait_group 0;" ::: "memory");
    __syncthreads();
    compute(S - 1);

    // ---------------- epilogue ----------------
#pragma unroll
    for (int mt = 0; mt < 2; mt++) {
        int local0 = wm * 32 + mt * 16 + (lane >> 2);
        int local1 = local0 + 8;
        bool v0 = (m0 + local0) < cnt;
        bool v1 = (m0 + local1) < cnt;
        size_t s0 = (size_t)(off + m0 + local0);
        size_t s1 = (size_t)(off + m0 + local1);
        if (MODE == 0) {
#pragma unroll
            for (int nt = 0; nt < 8; nt++) {
                int f = ((n0 + wn * 64 + nt * 8) >> 1) + (lane & 3);
                float g0 = acc[mt][nt][0], u0 = acc[mt][nt][1];
                float g1 = acc[mt][nt][2], u1 = acc[mt][nt][3];
                float h0 = g0 / (1.f + expf(-g0)) * u0;
                float h1 = g1 / (1.f + expf(-g1)) * u1;
                if (v0) g_h[s0 * F + f] = __float2half_rn(h0);
                if (v1) g_h[s1 * F + f] = __float2half_rn(h1);
            }
        } else {
#pragma unroll
            for (int nt = 0; nt < 8; nt++) {
                int col = n0 + wn * 64 + nt * 8 + (lane & 3) * 2;
                if (v0) *(float2*)&g_obuf[s0 * D + col] = make_float2(acc[mt][nt][0], acc[mt][nt][1]);
                if (v1) *(float2*)&g_obuf[s1 * D + col] = make_float2(acc[mt][nt][2], acc[mt][nt][3]);
            }
        }
    }
}

// ---------------- combine ----------------
__global__ void combine_kernel(float* __restrict__ out) {
    int t = blockIdx.x;
    float w0 = g_top_w[2 * t], w1 = g_top_w[2 * t + 1];
    const float* r0 = g_obuf + (size_t)g_slot[2 * t] * D;
    const float* r1 = g_obuf + (size_t)g_slot[2 * t + 1] * D;
    int c = threadIdx.x * 4;
    float4 a = *(const float4*)(r0 + c);
    float4 b = *(const float4*)(r1 + c);
    float4 o;
    o.x = w0 * a.x + w1 * b.x;
    o.y = w0 * a.y + w1 * b.y;
    o.z = w0 * a.z + w1 * b.z;
    o.w = w0 * a.w + w1 * b.w;
    *(float4*)(out + (size_t)t * D + c) = o;
}

// ---------------- launch ----------------
extern "C" void kernel_launch(void* const* d_in, const int* in_sizes, int n_in,
                              void* d_out, int out_size) {
    const float* x  = (const float*)d_in[0];
    const float* rw = (const float*)d_in[1];
    const float* gw = (const float*)d_in[2];
    const float* uw = (const float*)d_in[3];
    const float* dw = (const float*)d_in[4];
    float* out = (float*)d_out;

    cudaFuncSetAttribute(gemm_mma<0>, cudaFuncAttributeMaxDynamicSharedMemorySize, GEMM_SMEM);
    cudaFuncSetAttribute(gemm_mma<1>, cudaFuncAttributeMaxDynamicSharedMemorySize, GEMM_SMEM);

    prep_kernel<<<65536, 256>>>(gw, uw, dw);                    // 1
    router_kernel<<<T / 8, 256>>>(x, rw);                        // 2
    build_lists_kernel<<<1, 256>>>();                            // 3
    gemm_mma<0><<<dim3(64, 64, E), 256, GEMM_SMEM>>>();          // 4  <- profiled
    gemm_mma<1><<<dim3(64, 8, E), 256, GEMM_SMEM>>>();           // 5
    combine_kernel<<<T, 256>>>(out);                             // 6
}